// round 8
// baseline (speedup 1.0000x reference)
#include <cuda_runtime.h>
#include <cuda_fp16.h>
#include <cstdint>

// Masked LeNet-C3 conv via fp16 mma.sync.m16n8k16 (HMMA) implicit GEMM on sm_103.
// x: [64,6,512,512] f32, W: [16,6,5,5] f32, b: [16] f32 -> out: [64,16,508,508] f32
//
// Warp tile: M=64 px x N=16 oc, one output row. K-step = (ky, ic-pair), K=16 = 2 ics x 8 kx
// (kx 5..7 zero-padded weights). Input tile stored as fp16 interleaved ic-pair 8B blocks
// [ic0 c, ic0 c+1, ic1 c, ic1 c+1] in two column-shifted copies so every thread's A-fragment
// halves come from aligned LDS.64. Weight table pre-swizzled for LDS.64 B-fragments.

#define NIC 6
#define NOC 16
#define IH 512
#define IW 512
#define OH 508
#define OW 508
#define TILE_W 64
#define TILE_H 8
#define IN_ROWS 12
#define BLK_ROW 40                        // 8B blocks per row (cols 0..79)
#define COPY_BLKS (3 * IN_ROWS * BLK_ROW) // 1440
#define COPY_STRIDE (COPY_BLKS + 8)       // +8 blocks => +16 banks between copies
#define NSTEP 15
#define NTHREADS 256

typedef unsigned long long ull;

__host__ __device__ constexpr float conn(int ic, int oc) {
    constexpr int M[NIC][NOC] = {
        {1,0,0,0,1,1,1,0,0,1,1,1,1,0,1,1},
        {1,1,0,0,0,1,1,1,0,0,1,1,1,1,0,1},
        {1,1,1,0,0,0,1,1,1,0,0,1,0,1,1,1},
        {0,1,1,1,0,0,1,1,1,1,0,0,1,0,1,1},
        {0,0,1,1,1,0,0,1,1,1,1,0,1,1,0,1},
        {0,0,0,1,1,1,0,0,1,1,1,1,0,1,1,1},
    };
    return (float)M[ic][oc];
}

// pack two f32 -> f16x2 (lo = first arg)
__device__ __forceinline__ uint32_t pack_f16x2(float lo, float hi) {
    uint32_t r;
    asm("cvt.rn.f16x2.f32 %0, %1, %2;" : "=r"(r) : "f"(hi), "f"(lo));
    return r;
}

// D(16x8,f32) += A(16x16,f16) * B(16x8,f16)
__device__ __forceinline__ void mma_f16(float* d, const uint32_t* a,
                                        uint32_t b0, uint32_t b1) {
    asm("mma.sync.aligned.m16n8k16.row.col.f32.f16.f16.f32 "
        "{%0,%1,%2,%3}, {%4,%5,%6,%7}, {%8,%9}, {%0,%1,%2,%3};"
        : "+f"(d[0]), "+f"(d[1]), "+f"(d[2]), "+f"(d[3])
        : "r"(a[0]), "r"(a[1]), "r"(a[2]), "r"(a[3]), "r"(b0), "r"(b1));
}

__global__ __launch_bounds__(NTHREADS, 3)
void conv_c3_hmma(const float* __restrict__ x,
                  const float* __restrict__ W,
                  const float* __restrict__ b,
                  float* __restrict__ out)
{
    __shared__ __align__(16) ull      s_in[2 * COPY_STRIDE];      // 23168 B
    __shared__ __align__(16) uint32_t s_B[NSTEP * NOC * 8];       //  7680 B
    __shared__ float s_b[NOC];

    const int tid  = threadIdx.x;
    const int lane = tid & 31;
    const int warp = tid >> 5;
    const int n    = blockIdx.z;
    const int by0  = blockIdx.y * TILE_H;
    const int bx0  = blockIdx.x * TILE_W;

    // ---- Input tile -> fp16 interleaved ic-pair blocks, 2 shifted copies ----
    // copy cp block b covers cols (2b+cp, 2b+cp+1) for ics (2*icp, 2*icp+1)
    const float* xin = x + (size_t)n * NIC * IH * IW;
    #pragma unroll 1
    for (int idx = tid; idx < 2 * COPY_BLKS; idx += NTHREADS) {
        int cp   = idx / COPY_BLKS;
        int rem  = idx % COPY_BLKS;
        int icp  = rem / (IN_ROWS * BLK_ROW);
        int rem2 = rem % (IN_ROWS * BLK_ROW);
        int row  = rem2 / BLK_ROW;
        int bb   = rem2 % BLK_ROW;
        int c0   = 2 * bb + cp;
        int gy   = by0 + row;
        int gx0  = bx0 + c0;

        float v00 = 0.f, v01 = 0.f, v10 = 0.f, v11 = 0.f;
        if (gy < IH) {
            const float* p0 = xin + ((size_t)(2 * icp) * IH + gy) * IW;
            const float* p1 = p0 + (size_t)IH * IW;
            if (gx0 < IW)     { v00 = __ldg(p0 + gx0);     v10 = __ldg(p1 + gx0); }
            if (gx0 + 1 < IW) { v01 = __ldg(p0 + gx0 + 1); v11 = __ldg(p1 + gx0 + 1); }
        }
        uint32_t lo = pack_f16x2(v00, v01);   // ic0: cols c0, c0+1
        uint32_t hi = pack_f16x2(v10, v11);   // ic1: cols c0, c0+1
        s_in[cp * COPY_STRIDE + icp * (IN_ROWS * BLK_ROW) + row * BLK_ROW + bb] =
            ((ull)hi << 32) | (ull)lo;
    }

    // ---- Weight table: step s=(ky*3+icp); per oc 8 u32: [j][half=ic_local] ----
    // u32 at s*128 + oc*8 + j*2 + half = f16x2( W(ic,ky,2j), W(ic,ky,2j+1) ), kx>=5 -> 0
    #pragma unroll 1
    for (int idx = tid; idx < NSTEP * NOC * 8; idx += NTHREADS) {
        int half = idx & 1;
        int j    = (idx >> 1) & 3;
        int oc   = (idx >> 3) & 15;
        int s    = idx >> 7;
        int ky   = s / 3;
        int ic   = 2 * (s % 3) + half;
        int kx0  = 2 * j;
        float w0 = (kx0 < 5)     ? W[oc * (NIC*25) + ic * 25 + ky * 5 + kx0]     * conn(ic, oc) : 0.f;
        float w1 = (kx0 + 1 < 5) ? W[oc * (NIC*25) + ic * 25 + ky * 5 + kx0 + 1] * conn(ic, oc) : 0.f;
        s_B[idx] = pack_f16x2(w0, w1);
    }
    if (tid < NOC) s_b[tid] = b[tid];
    __syncthreads();

    // ---- Main loop ----
    const int g  = lane >> 2;
    const int c4 = lane & 3;
    const int p  = g & 1;                       // copy selector (alignment parity)
    const int wy = warp;                        // output row within tile
    // thread A-block base: b_t = (g-p)/2 + c4 in copy p
    const ull* abase = s_in + p * COPY_STRIDE + ((g - p) >> 1) + c4;

    float acc[4][2][4];
    #pragma unroll
    for (int mt = 0; mt < 4; mt++)
        #pragma unroll
        for (int h = 0; h < 2; h++)
            #pragma unroll
            for (int i = 0; i < 4; i++) acc[mt][h][i] = 0.f;

    #pragma unroll 1
    for (int ky = 0; ky < 5; ky++) {
        #pragma unroll
        for (int icp = 0; icp < 3; icp++) {
            const int s = ky * 3 + icp;
            // B fragments: one LDS.64 each for oc 0..7 and oc 8..15
            ull blv = *(const ull*)(s_B + s * 128 + g * 8 + c4 * 2);
            ull bhv = *(const ull*)(s_B + s * 128 + 64 + g * 8 + c4 * 2);
            uint32_t bL0 = (uint32_t)blv, bL1 = (uint32_t)(blv >> 32);
            uint32_t bH0 = (uint32_t)bhv, bH1 = (uint32_t)(bhv >> 32);
            const ull* ap = abase + (icp * IN_ROWS + wy + ky) * BLK_ROW;
            #pragma unroll
            for (int mt = 0; mt < 4; mt++) {
                ull a02 = ap[8 * mt];        // rows m=g..: (a0, a2)
                ull a13 = ap[8 * mt + 4];    // rows m=g+8: (a1, a3)
                uint32_t A[4];
                A[0] = (uint32_t)a02;
                A[1] = (uint32_t)a13;
                A[2] = (uint32_t)(a02 >> 32);
                A[3] = (uint32_t)(a13 >> 32);
                mma_f16(acc[mt][0], A, bL0, bL1);
                mma_f16(acc[mt][1], A, bH0, bH1);
            }
        }
    }

    // ---- Epilogue ----
    const int y = by0 + wy;
    if (y < OH) {
        #pragma unroll
        for (int half = 0; half < 2; half++) {
            int oc0 = half * 8 + 2 * c4;
            float bo0 = s_b[oc0], bo1 = s_b[oc0 + 1];
            #pragma unroll
            for (int mt = 0; mt < 4; mt++) {
                int x0 = bx0 + mt * 16 + g;
                size_t base0 = (((size_t)n * NOC + oc0) * OH + y) * OW;
                size_t base1 = base0 + (size_t)OH * OW;
                if (x0 < OW) {
                    out[base0 + x0] = acc[mt][half][0] + bo0;
                    out[base1 + x0] = acc[mt][half][1] + bo1;
                }
                if (x0 + 8 < OW) {
                    out[base0 + x0 + 8] = acc[mt][half][2] + bo0;
                    out[base1 + x0 + 8] = acc[mt][half][3] + bo1;
                }
            }
        }
    }
}

extern "C" void kernel_launch(void* const* d_in, const int* in_sizes, int n_in,
                              void* d_out, int out_size) {
    const float* x = (const float*)d_in[0];
    const float* W = (const float*)d_in[1];
    const float* b = (const float*)d_in[2];
    float* out = (float*)d_out;

    const int n_batch = in_sizes[0] / (NIC * IH * IW);   // 64
    dim3 grid((OW + TILE_W - 1) / TILE_W,    // 8
              (OH + TILE_H - 1) / TILE_H,    // 64
              n_batch);                       // 64
    conv_c3_hmma<<<grid, NTHREADS>>>(x, W, b, out);
}

// round 9
// speedup vs baseline: 1.0164x; 1.0164x over previous
#include <cuda_runtime.h>
#include <cuda_fp16.h>
#include <cstdint>

// Masked LeNet-C3 conv via fp16 mma.sync.m16n8k16 (HMMA) implicit GEMM on sm_103.
// x: [64,6,512,512] f32, W: [16,6,5,5] f32, b: [16] f32 -> out: [64,16,508,508] f32
//
// Round 9: identical compute loop to round 8 (layout proven, rel_err 2.9e-4);
// loader rewritten: coalesced f32 LDG (1 elem/thread) + scattered STS.16 into the
// two interleaved fp16 copies, after a cheap zero-init. Fixes the L2=70% loader bound.

#define NIC 6
#define NOC 16
#define IH 512
#define IW 512
#define OH 508
#define OW 508
#define TILE_W 64
#define TILE_H 8
#define IN_ROWS 12
#define LCOLS 68                          // loaded cols 0..67 (64 + 4 halo)
#define BLK_ROW 40                        // 8B blocks per row (cols 0..79; >67 stay zero)
#define COPY_BLKS (3 * IN_ROWS * BLK_ROW) // 1440
#define COPY_STRIDE (COPY_BLKS + 8)       // +8 blocks => +16 banks between copies
#define NSTEP 15
#define NTHREADS 256

typedef unsigned long long ull;

__host__ __device__ constexpr float conn(int ic, int oc) {
    constexpr int M[NIC][NOC] = {
        {1,0,0,0,1,1,1,0,0,1,1,1,1,0,1,1},
        {1,1,0,0,0,1,1,1,0,0,1,1,1,1,0,1},
        {1,1,1,0,0,0,1,1,1,0,0,1,0,1,1,1},
        {0,1,1,1,0,0,1,1,1,1,0,0,1,0,1,1},
        {0,0,1,1,1,0,0,1,1,1,1,0,1,1,0,1},
        {0,0,0,1,1,1,0,0,1,1,1,1,0,1,1,1},
    };
    return (float)M[ic][oc];
}

__device__ __forceinline__ uint32_t pack_f16x2(float lo, float hi) {
    uint32_t r;
    asm("cvt.rn.f16x2.f32 %0, %1, %2;" : "=r"(r) : "f"(hi), "f"(lo));
    return r;
}

// D(16x8,f32) += A(16x16,f16) * B(16x8,f16)
__device__ __forceinline__ void mma_f16(float* d, const uint32_t* a,
                                        uint32_t b0, uint32_t b1) {
    asm("mma.sync.aligned.m16n8k16.row.col.f32.f16.f16.f32 "
        "{%0,%1,%2,%3}, {%4,%5,%6,%7}, {%8,%9}, {%0,%1,%2,%3};"
        : "+f"(d[0]), "+f"(d[1]), "+f"(d[2]), "+f"(d[3])
        : "r"(a[0]), "r"(a[1]), "r"(a[2]), "r"(a[3]), "r"(b0), "r"(b1));
}

__global__ __launch_bounds__(NTHREADS, 3)
void conv_c3_hmma(const float* __restrict__ x,
                  const float* __restrict__ W,
                  const float* __restrict__ b,
                  float* __restrict__ out)
{
    __shared__ __align__(16) ull      s_in[2 * COPY_STRIDE];      // 23168 B
    __shared__ __align__(16) uint32_t s_B[NSTEP * NOC * 8];       //  7680 B
    __shared__ float s_b[NOC];

    const int tid  = threadIdx.x;
    const int lane = tid & 31;
    const int warp = tid >> 5;
    const int n    = blockIdx.z;
    const int by0  = blockIdx.y * TILE_H;
    const int bx0  = blockIdx.x * TILE_W;

    // ---- Zero-init interleaved region (cols >= 68 and copy-1 col 0 must be 0) ----
    #pragma unroll 1
    for (int i = tid; i < 2 * COPY_STRIDE; i += NTHREADS) s_in[i] = 0ull;

    // ---- Weight table: step s=(ky*3+icp); per oc 8 u32: [j][half=ic_local] ----
    #pragma unroll 1
    for (int idx = tid; idx < NSTEP * NOC * 8; idx += NTHREADS) {
        int half = idx & 1;
        int j    = (idx >> 1) & 3;
        int oc   = (idx >> 3) & 15;
        int s    = idx >> 7;
        int ky   = s / 3;
        int ic   = 2 * (s % 3) + half;
        int kx0  = 2 * j;
        float w0 = (kx0 < 5)     ? W[oc * (NIC*25) + ic * 25 + ky * 5 + kx0]     * conn(ic, oc) : 0.f;
        float w1 = (kx0 + 1 < 5) ? W[oc * (NIC*25) + ic * 25 + ky * 5 + kx0 + 1] * conn(ic, oc) : 0.f;
        s_B[idx] = pack_f16x2(w0, w1);
    }
    if (tid < NOC) s_b[tid] = b[tid];
    __syncthreads();

    // ---- Input tile: coalesced f32 LDG, fp16 convert, scatter STS.16 x2 ----
    // block layout (8B): hw0=ic0@c0, hw1=ic0@c0+1, hw2=ic1@c0, hw3=ic1@c0+1
    // copy0: c0 = 2b;  copy1: c0 = 2b+1
    const float* xin = x + (size_t)n * NIC * IH * IW;
    unsigned short* hw = (unsigned short*)s_in;
    #pragma unroll 1
    for (int idx = tid; idx < NIC * IN_ROWS * LCOLS; idx += NTHREADS) {
        int col = idx % LCOLS;
        int row = (idx / LCOLS) % IN_ROWS;
        int ic  = idx / (LCOLS * IN_ROWS);
        int gy  = by0 + row;
        int gx  = bx0 + col;
        float v = 0.f;
        if (gy < IH && gx < IW)
            v = __ldg(&xin[((size_t)ic * IH + gy) * IW + gx]);
        unsigned short hb = __half_as_ushort(__float2half_rn(v));
        int icp = ic >> 1, icl = ic & 1;
        int rowbase = icp * (IN_ROWS * BLK_ROW) + row * BLK_ROW;
        // copy 0
        hw[(rowbase + (col >> 1)) * 4 + 2 * icl + (col & 1)] = hb;
        // copy 1 (covers cols >= 1)
        if (col >= 1)
            hw[(COPY_STRIDE + rowbase + ((col - 1) >> 1)) * 4 + 2 * icl + ((col - 1) & 1)] = hb;
    }
    __syncthreads();

    // ---- Main loop (identical to round 8) ----
    const int g  = lane >> 2;
    const int c4 = lane & 3;
    const int p  = g & 1;                       // copy selector (alignment parity)
    const int wy = warp;                        // output row within tile
    const ull* abase = s_in + p * COPY_STRIDE + ((g - p) >> 1) + c4;

    float acc[4][2][4];
    #pragma unroll
    for (int mt = 0; mt < 4; mt++)
        #pragma unroll
        for (int h = 0; h < 2; h++)
            #pragma unroll
            for (int i = 0; i < 4; i++) acc[mt][h][i] = 0.f;

    #pragma unroll 1
    for (int ky = 0; ky < 5; ky++) {
        #pragma unroll
        for (int icp = 0; icp < 3; icp++) {
            const int s = ky * 3 + icp;
            ull blv = *(const ull*)(s_B + s * 128 + g * 8 + c4 * 2);
            ull bhv = *(const ull*)(s_B + s * 128 + 64 + g * 8 + c4 * 2);
            uint32_t bL0 = (uint32_t)blv, bL1 = (uint32_t)(blv >> 32);
            uint32_t bH0 = (uint32_t)bhv, bH1 = (uint32_t)(bhv >> 32);
            const ull* ap = abase + (icp * IN_ROWS + wy + ky) * BLK_ROW;
            #pragma unroll
            for (int mt = 0; mt < 4; mt++) {
                ull a02 = ap[8 * mt];        // rows m=g..: (a0, a2)
                ull a13 = ap[8 * mt + 4];    // rows m=g+8: (a1, a3)
                uint32_t A[4];
                A[0] = (uint32_t)a02;
                A[1] = (uint32_t)a13;
                A[2] = (uint32_t)(a02 >> 32);
                A[3] = (uint32_t)(a13 >> 32);
                mma_f16(acc[mt][0], A, bL0, bL1);
                mma_f16(acc[mt][1], A, bH0, bH1);
            }
        }
    }

    // ---- Epilogue ----
    const int y = by0 + wy;
    if (y < OH) {
        #pragma unroll
        for (int half = 0; half < 2; half++) {
            int oc0 = half * 8 + 2 * c4;
            float bo0 = s_b[oc0], bo1 = s_b[oc0 + 1];
            #pragma unroll
            for (int mt = 0; mt < 4; mt++) {
                int x0 = bx0 + mt * 16 + g;
                size_t base0 = (((size_t)n * NOC + oc0) * OH + y) * OW;
                size_t base1 = base0 + (size_t)OH * OW;
                if (x0 < OW) {
                    out[base0 + x0] = acc[mt][half][0] + bo0;
                    out[base1 + x0] = acc[mt][half][1] + bo1;
                }
                if (x0 + 8 < OW) {
                    out[base0 + x0 + 8] = acc[mt][half][2] + bo0;
                    out[base1 + x0 + 8] = acc[mt][half][3] + bo1;
                }
            }
        }
    }
}

extern "C" void kernel_launch(void* const* d_in, const int* in_sizes, int n_in,
                              void* d_out, int out_size) {
    const float* x = (const float*)d_in[0];
    const float* W = (const float*)d_in[1];
    const float* b = (const float*)d_in[2];
    float* out = (float*)d_out;

    const int n_batch = in_sizes[0] / (NIC * IH * IW);   // 64
    dim3 grid((OW + TILE_W - 1) / TILE_W,    // 8
              (OH + TILE_H - 1) / TILE_H,    // 64
              n_batch);                       // 64
    conv_c3_hmma<<<grid, NTHREADS>>>(x, W, b, out);
}